// round 2
// baseline (speedup 1.0000x reference)
#include <cuda_runtime.h>
#include <math.h>

#define Bn 4
#define Tn 8192
#define Dn 1024
#define Hn 8
#define HDm 128
#define Cc 64
#define Nc 128
#define BT (Bn*Tn)
#define BH (Bn*Hn)
#define PAD 132
#define ESPLIT 4

// ---------------- scratch (device globals; no runtime allocation) ----------------
__device__ float g_rk  [(size_t)BH*Tn*HDm];   // normalized read keys   (B,H,T,d)
__device__ float g_wk  [(size_t)BH*Tn*HDm];   // shifted write keys     (B,H,T,d)
__device__ float g_v   [(size_t)BH*Tn*HDm];   // v (beta-scaled, then UT-transformed in place)
__device__ float g_wkcd[(size_t)BH*Tn*HDm];   // A @ (wk*beta*exp(dec))
__device__ float g_o   [(size_t)BT*Dn];       // gated output, (B,T,D)
__device__ float g_attn[(size_t)BH*Nc*Cc*Cc]; // intra-chunk attention (precomputed, S-independent)
__device__ float g_dec   [(size_t)BH*Tn];     // cumulative log-decay per chunk, (B,H,N,C)
__device__ float g_decraw[(size_t)BH*Tn];
__device__ float g_beta  [(size_t)BH*Tn];     // (B,H,T)
__device__ float g_gate  [(size_t)BT*Hn];     // (B,T,H)

static __device__ __forceinline__ float4 ldf4(const float* p) { return *(const float4*)p; }
static __device__ __forceinline__ void stf4(float* p, float4 v) { *(float4*)p = v; }

// ---------------- K1: gate/beta/decay projections ----------------
__global__ __launch_bounds__(256) void k_proj_small(
    const float* __restrict__ x, const float* __restrict__ Wg,
    const float* __restrict__ Wb, const float* __restrict__ Wa,
    const float* __restrict__ dtb, const float* __restrict__ Alog)
{
    int row = blockIdx.x;             // b*T + t
    int tid = threadIdx.x;
    __shared__ float sx[Dn];
    ((float4*)sx)[tid] = ((const float4*)(x + (size_t)row*Dn))[tid];
    __syncthreads();
    int w = tid >> 5, lane = tid & 31;   // warp w -> head w
    const float* wg = Wg + (size_t)w*Dn;
    const float* wb = Wb + (size_t)w*Dn;
    const float* wa = Wa + (size_t)w*Dn;
    float dg = 0.f, db = 0.f, da = 0.f;
    for (int k = lane*4; k < Dn; k += 128) {
        float4 xv = ldf4(sx + k);
        float4 g4 = ldf4(wg + k);
        float4 b4 = ldf4(wb + k);
        float4 a4 = ldf4(wa + k);
        dg += xv.x*g4.x + xv.y*g4.y + xv.z*g4.z + xv.w*g4.w;
        db += xv.x*b4.x + xv.y*b4.y + xv.z*b4.z + xv.w*b4.w;
        da += xv.x*a4.x + xv.y*a4.y + xv.z*a4.z + xv.w*a4.w;
    }
    #pragma unroll
    for (int o = 16; o; o >>= 1) {
        dg += __shfl_down_sync(0xffffffffu, dg, o);
        db += __shfl_down_sync(0xffffffffu, db, o);
        da += __shfl_down_sync(0xffffffffu, da, o);
    }
    if (lane == 0) {
        int b = row / Tn, t = row % Tn;
        g_gate[(size_t)row*Hn + w] = 1.f / (1.f + expf(-dg));
        size_t idx = (size_t)(b*Hn + w)*Tn + t;
        g_beta[idx] = 1.f / (1.f + expf(-db));
        float z = da + dtb[w];
        float sp = (z > 20.f) ? z : log1pf(expf(z));
        g_decraw[idx] = -expf(Alog[w]) * sp;
    }
}

// ---------------- K2: normalized read keys + token-shifted write keys ----------------
__global__ __launch_bounds__(256) void k_rkwk(const float* __restrict__ x)
{
    int row = blockIdx.x;             // b*T + t
    int b = row / Tn, t = row % Tn;
    int tid = threadIdx.x, w = tid >> 5, lane = tid & 31;
    const float* xr = x + (size_t)row*Dn + w*HDm;
    float4 v = ((const float4*)xr)[lane];
    float ss = v.x*v.x + v.y*v.y + v.z*v.z + v.w*v.w;
    #pragma unroll
    for (int o = 16; o; o >>= 1) ss += __shfl_xor_sync(0xffffffffu, ss, o);
    float inv = 1.f / fmaxf(sqrtf(ss), 1e-12f);
    float4 r = make_float4(v.x*inv, v.y*inv, v.z*inv, v.w*inv);
    size_t base = (size_t)(b*Hn + w)*Tn;
    ((float4*)(g_rk + (base + t)*HDm))[lane] = r;
    if (t + 1 < Tn) ((float4*)(g_wk + (base + t + 1)*HDm))[lane] = r;
    if (t == 0) {
        float4 z = make_float4(0.f, 0.f, 0.f, 0.f);
        ((float4*)(g_wk + base*HDm))[lane] = z;
    }
}

// ---------------- K3: per-chunk cumulative decay ----------------
__global__ void k_cumsum()
{
    int idx = blockIdx.x*blockDim.x + threadIdx.x;   // (b*H+h)*N + n
    if (idx >= BH*Nc) return;
    const float* src = g_decraw + (size_t)idx*Cc;
    float* dst = g_dec + (size_t)idx*Cc;
    float s = 0.f;
    for (int c = 0; c < Cc; c++) { s += src[c]; dst[c] = s; }
}

// ---------------- K4: v = (x @ W_write^T) * beta, scattered to (B,H,T,d) ----------------
__global__ __launch_bounds__(256) void k_gemm_v(const float* __restrict__ A,
                                                const float* __restrict__ W)
{
    __shared__ float As[16][68];
    __shared__ float Bs[16][68];
    int tid = threadIdx.x;
    int r0 = blockIdx.y*64, c0 = blockIdx.x*64;
    int tx = tid & 15, ty = tid >> 4;
    int lr = tid >> 2, kq = tid & 3;
    float acc[4][4] = {};
    const float* Ap = A + (size_t)(r0 + lr)*Dn + kq*4;
    const float* Wp = W + (size_t)(c0 + lr)*Dn + kq*4;
    for (int k0 = 0; k0 < Dn; k0 += 16) {
        float4 av = ldf4(Ap + k0);
        float4 bv = ldf4(Wp + k0);
        As[kq*4+0][lr]=av.x; As[kq*4+1][lr]=av.y; As[kq*4+2][lr]=av.z; As[kq*4+3][lr]=av.w;
        Bs[kq*4+0][lr]=bv.x; Bs[kq*4+1][lr]=bv.y; Bs[kq*4+2][lr]=bv.z; Bs[kq*4+3][lr]=bv.w;
        __syncthreads();
        #pragma unroll
        for (int k = 0; k < 16; k++) {
            float4 ra = ldf4(&As[k][ty*4]);
            float4 rb = ldf4(&Bs[k][tx*4]);
            float a_[4] = {ra.x, ra.y, ra.z, ra.w};
            float b_[4] = {rb.x, rb.y, rb.z, rb.w};
            #pragma unroll
            for (int i = 0; i < 4; i++)
                #pragma unroll
                for (int j = 0; j < 4; j++)
                    acc[i][j] += a_[i]*b_[j];
        }
        __syncthreads();
    }
    int b = r0 / Tn;
    int h = c0 / HDm;
    int kk0 = (c0 % HDm) + tx*4;
    #pragma unroll
    for (int i = 0; i < 4; i++) {
        int t = (r0 % Tn) + ty*4 + i;
        size_t bht = (size_t)(b*Hn + h)*Tn + t;
        float bb = g_beta[bht];
        stf4(g_v + bht*HDm + kk0,
             make_float4(acc[i][0]*bb, acc[i][1]*bb, acc[i][2]*bb, acc[i][3]*bb));
    }
}

// ---------------- K5: per-chunk UT transform + attn precompute ----------------
// smem floats: 3*64*PAD + 128*64 + 64*68 + 192 = 38080  (152320 B)
#define SMEM_CHUNK (size_t)((3*64*PAD + 128*64 + 64*68 + 192)*4)
__global__ __launch_bounds__(256) void k_chunk()
{
    extern __shared__ float sm[];
    float* s_wk   = sm;                 // 64*PAD
    float* s_rk   = s_wk  + 64*PAD;
    float* s_v    = s_rk  + 64*PAD;
    float* s_wkT  = s_v   + 64*PAD;     // 128*64 (k-major wk for conflict-free B operand)
    float* s_M    = s_wkT + 128*64;     // 64*68  (M -> A in place, strict lower)
    float* s_dec  = s_M   + 64*68;      // 64
    float* s_beta = s_dec + 64;
    float* s_edec = s_beta + 64;

    int chunk = blockIdx.x;             // (b*H+h)*N + n
    size_t base = (size_t)chunk*(Cc*HDm);
    int tid = threadIdx.x;

    for (int i4 = tid; i4 < 64*32; i4 += 256) {
        int r = i4 >> 5, c4 = (i4 & 31)*4;
        float4 wv = ldf4(g_wk + base + (size_t)r*HDm + c4);
        stf4(s_wk + r*PAD + c4, wv);
        s_wkT[(c4+0)*64 + r] = wv.x;
        s_wkT[(c4+1)*64 + r] = wv.y;
        s_wkT[(c4+2)*64 + r] = wv.z;
        s_wkT[(c4+3)*64 + r] = wv.w;
        stf4(s_rk + r*PAD + c4, ldf4(g_rk + base + (size_t)r*HDm + c4));
        stf4(s_v  + r*PAD + c4, ldf4(g_v  + base + (size_t)r*HDm + c4));
    }
    if (tid < 64) {
        s_dec[tid]  = g_dec [(size_t)chunk*Cc + tid];
        s_beta[tid] = g_beta[(size_t)chunk*Cc + tid];
    }
    __syncthreads();
    if (tid < 64) s_edec[tid] = expf(s_dec[tid]);

    // ---- M (strict lower, beta*exp masked) and attn (incl. diag), both 64x64 ----
    int j0 = (tid & 15)*4;
    int ibase = tid >> 4;
    #pragma unroll
    for (int ib = 0; ib < 4; ib++) {
        int i = ibase + 16*ib;
        float mA[4] = {0,0,0,0};
        float aA[4] = {0,0,0,0};
        const float* wkr = s_wk + i*PAD;
        const float* rkr = s_rk + i*PAD;
        for (int k = 0; k < HDm; k++) {
            float wik = wkr[k], rik = rkr[k];
            float4 wj = ldf4(s_wkT + k*64 + j0);
            mA[0] += wik*wj.x; mA[1] += wik*wj.y; mA[2] += wik*wj.z; mA[3] += wik*wj.w;
            aA[0] += rik*wj.x; aA[1] += rik*wj.y; aA[2] += rik*wj.z; aA[3] += rik*wj.w;
        }
        float di = s_dec[i], bi = s_beta[i];
        float av[4], mv[4];
        #pragma unroll
        for (int q = 0; q < 4; q++) {
            int j = j0 + q;
            float e = expf(di - s_dec[j]);
            av[q] = (j <= i) ? aA[q]*e : 0.f;
            mv[q] = (j <  i) ? mA[q]*bi*e : 0.f;
        }
        stf4(g_attn + (size_t)chunk*(Cc*Cc) + (size_t)i*Cc + j0,
             make_float4(av[0], av[1], av[2], av[3]));
        stf4(s_M + i*68 + j0, make_float4(mv[0], mv[1], mv[2], mv[3]));
    }
    __syncthreads();

    // ---- forward substitution: A = (I+M)^-1, strict lower in place ----
    for (int i = 1; i < Cc; i++) {
        float a = 0.f;
        if (tid < i) {
            a = s_M[i*68 + tid];
            for (int k = tid + 1; k < i; k++)
                a += s_M[i*68 + k] * s_M[k*68 + tid];
            a = -a;
        }
        __syncthreads();
        if (tid < i) s_M[i*68 + tid] = a;
        __syncthreads();
    }

    // ---- v_new = A @ v ; wkcd = A @ (wk*beta*exp(dec)) ----
    int k0 = (tid & 31)*4;
    int cbase = tid >> 5;
    #pragma unroll
    for (int cb = 0; cb < 8; cb++) {
        int c = cbase + 8*cb;
        float4 vac = ldf4(s_v + c*PAD + k0);
        float cw = s_beta[c]*s_edec[c];
        float4 wc = ldf4(s_wk + c*PAD + k0);
        float4 wac = make_float4(wc.x*cw, wc.y*cw, wc.z*cw, wc.w*cw);
        for (int j = 0; j < c; j++) {
            float aa = s_M[c*68 + j];
            float4 vj = ldf4(s_v + j*PAD + k0);
            float4 wj = ldf4(s_wk + j*PAD + k0);
            float cj = aa * s_beta[j] * s_edec[j];
            vac.x += aa*vj.x; vac.y += aa*vj.y; vac.z += aa*vj.z; vac.w += aa*vj.w;
            wac.x += cj*wj.x; wac.y += cj*wj.y; wac.z += cj*wj.z; wac.w += cj*wj.w;
        }
        stf4(g_v    + base + (size_t)c*HDm + k0, vac);
        stf4(g_wkcd + base + (size_t)c*HDm + k0, wac);
    }
}

// ---------------- K6: sequential inter-chunk scan (state S), e-split x4 ----------------
// smem floats: 128*32 + 3*64*PAD + 64*68 + 64*32 + 208 = 36096  (144384 B)
#define SMEM_SCAN (size_t)((128*32 + 3*64*PAD + 64*68 + 64*32 + 208)*4)
__global__ __launch_bounds__(256) void k_scan()
{
    extern __shared__ float sm[];
    float* s_S    = sm;                    // 128*32
    float* s_rk   = s_S    + 128*32;       // 64*PAD
    float* s_wk   = s_rk   + 64*PAD;
    float* s_wkcd = s_wk   + 64*PAD;
    float* s_attn = s_wkcd + 64*PAD;       // 64*68
    float* s_vnew = s_attn + 64*68;        // 64*32
    float* s_dec  = s_vnew + 64*32;        // 64
    float* s_edec = s_dec  + 64;
    float* s_coef = s_edec + 64;
    float* s_edl  = s_coef + 64;           // 16 slack

    int bh = blockIdx.x >> 2;
    int es = blockIdx.x & 3;
    int b = bh / Hn, h = bh % Hn;
    int tid = threadIdx.x;
    for (int i = tid; i < 128*32; i += 256) s_S[i] = 0.f;

    int e4 = tid & 7;
    int eoff = e4*4;
    int cA = tid >> 3;                     // 0..31
    int ecol = es*32 + eoff;
    size_t bhbase = (size_t)bh*Tn*HDm;

    for (int n = 0; n < Nc; n++) {
        size_t cb = bhbase + (size_t)n*Cc*HDm;
        for (int i4 = tid; i4 < 64*32; i4 += 256) {
            int r = i4 >> 5, c4 = (i4 & 31)*4;
            stf4(s_rk   + r*PAD + c4, ldf4(g_rk   + cb + (size_t)r*HDm + c4));
            stf4(s_wk   + r*PAD + c4, ldf4(g_wk   + cb + (size_t)r*HDm + c4));
            stf4(s_wkcd + r*PAD + c4, ldf4(g_wkcd + cb + (size_t)r*HDm + c4));
        }
        size_t ab = ((size_t)bh*Nc + n)*(Cc*Cc);
        for (int i4 = tid; i4 < 64*16; i4 += 256) {
            int r = i4 >> 4, c4 = (i4 & 15)*4;
            stf4(s_attn + r*68 + c4, ldf4(g_attn + ab + (size_t)r*Cc + c4));
        }
        if (tid < 64) s_dec[tid] = g_dec[((size_t)bh*Nc + n)*Cc + tid];
        __syncthreads();
        if (tid < 64) {
            float dl = s_dec[63];
            s_edec[tid] = expf(s_dec[tid]);
            s_coef[tid] = expf(dl - s_dec[tid]);
            if (tid == 0) s_edl[0] = expf(dl);
        }
        // ---- Phase A: v_new = v - wkcd @ S ----
        float4 va0 = ldf4(g_v + cb + (size_t)cA*HDm + ecol);
        float4 va1 = ldf4(g_v + cb + (size_t)(cA+32)*HDm + ecol);
        for (int k = 0; k < HDm; k++) {
            float4 S4 = ldf4(s_S + k*32 + eoff);
            float w0 = s_wkcd[cA*PAD + k];
            float w1 = s_wkcd[(cA+32)*PAD + k];
            va0.x -= w0*S4.x; va0.y -= w0*S4.y; va0.z -= w0*S4.z; va0.w -= w0*S4.w;
            va1.x -= w1*S4.x; va1.y -= w1*S4.y; va1.z -= w1*S4.z; va1.w -= w1*S4.w;
        }
        stf4(s_vnew + cA*32 + eoff, va0);
        stf4(s_vnew + (cA+32)*32 + eoff, va1);
        __syncthreads();
        // ---- Phase B: o = (rk*exp(dec)) @ S + attn @ v_new, gated ----
        float4 p0 = make_float4(0,0,0,0), p1 = make_float4(0,0,0,0);
        for (int k = 0; k < HDm; k++) {
            float4 S4 = ldf4(s_S + k*32 + eoff);
            float r0v = s_rk[cA*PAD + k];
            float r1v = s_rk[(cA+32)*PAD + k];
            p0.x += r0v*S4.x; p0.y += r0v*S4.y; p0.z += r0v*S4.z; p0.w += r0v*S4.w;
            p1.x += r1v*S4.x; p1.y += r1v*S4.y; p1.z += r1v*S4.z; p1.w += r1v*S4.w;
        }
        float ed0 = s_edec[cA], ed1 = s_edec[cA+32];
        float4 o0 = make_float4(p0.x*ed0, p0.y*ed0, p0.z*ed0, p0.w*ed0);
        float4 o1 = make_float4(p1.x*ed1, p1.y*ed1, p1.z*ed1, p1.w*ed1);
        for (int j = 0; j < Cc; j++) {                 // attn upper triangle is 0
            float4 vn = ldf4(s_vnew + j*32 + eoff);
            float a0 = s_attn[cA*68 + j];
            float a1 = s_attn[(cA+32)*68 + j];
            o0.x += a0*vn.x; o0.y += a0*vn.y; o0.z += a0*vn.z; o0.w += a0*vn.w;
            o1.x += a1*vn.x; o1.y += a1*vn.y; o1.z += a1*vn.z; o1.w += a1*vn.w;
        }
        {
            int t0 = n*Cc + cA, t1 = t0 + 32;
            float gg0 = g_gate[((size_t)b*Tn + t0)*Hn + h];
            float gg1 = g_gate[((size_t)b*Tn + t1)*Hn + h];
            o0.x *= gg0; o0.y *= gg0; o0.z *= gg0; o0.w *= gg0;
            o1.x *= gg1; o1.y *= gg1; o1.z *= gg1; o1.w *= gg1;
            stf4(g_o + ((size_t)b*Tn + t0)*Dn + h*HDm + ecol, o0);
            stf4(g_o + ((size_t)b*Tn + t1)*Dn + h*HDm + ecol, o1);
        }
        __syncthreads();
        // ---- Phase C: S = S*exp(dec_last) + (wk*exp(dec_last-dec))^T @ v_new ----
        float edl = s_edl[0];
        #pragma unroll
        for (int q = 0; q < 4; q++) {
            int k = cA + 32*q;
            float4 s4 = ldf4(s_S + k*32 + eoff);
            s4.x *= edl; s4.y *= edl; s4.z *= edl; s4.w *= edl;
            for (int c = 0; c < Cc; c++) {
                float wc = s_wk[c*PAD + k] * s_coef[c];
                float4 vn = ldf4(s_vnew + c*32 + eoff);
                s4.x += wc*vn.x; s4.y += wc*vn.y; s4.z += wc*vn.z; s4.w += wc*vn.w;
            }
            stf4(s_S + k*32 + eoff, s4);
        }
        __syncthreads();
    }
}

// ---------------- K7: out = x + o @ W_out^T ----------------
__global__ __launch_bounds__(256) void k_gemm_out(const float* __restrict__ W,
                                                  const float* __restrict__ x,
                                                  float* __restrict__ out)
{
    __shared__ float As[16][68];
    __shared__ float Bs[16][68];
    int tid = threadIdx.x;
    int r0 = blockIdx.y*64, c0 = blockIdx.x*64;
    int tx = tid & 15, ty = tid >> 4;
    int lr = tid >> 2, kq = tid & 3;
    float acc[4][4] = {};
    const float* Ap = g_o + (size_t)(r0 + lr)*Dn + kq*4;
    const float* Wp = W + (size_t)(c0 + lr)*Dn + kq*4;
    for (int k0 = 0; k0 < Dn; k0 += 16) {
        float4 av = ldf4(Ap + k0);
        float4 bv = ldf4(Wp + k0);
        As[kq*4+0][lr]=av.x; As[kq*4+1][lr]=av.y; As[kq*4+2][lr]=av.z; As[kq*4+3][lr]=av.w;
        Bs[kq*4+0][lr]=bv.x; Bs[kq*4+1][lr]=bv.y; Bs[kq*4+2][lr]=bv.z; Bs[kq*4+3][lr]=bv.w;
        __syncthreads();
        #pragma unroll
        for (int k = 0; k < 16; k++) {
            float4 ra = ldf4(&As[k][ty*4]);
            float4 rb = ldf4(&Bs[k][tx*4]);
            float a_[4] = {ra.x, ra.y, ra.z, ra.w};
            float b_[4] = {rb.x, rb.y, rb.z, rb.w};
            #pragma unroll
            for (int i = 0; i < 4; i++)
                #pragma unroll
                for (int j = 0; j < 4; j++)
                    acc[i][j] += a_[i]*b_[j];
        }
        __syncthreads();
    }
    #pragma unroll
    for (int i = 0; i < 4; i++) {
        size_t row = (size_t)r0 + ty*4 + i;
        float4 xv = ldf4(x + row*Dn + c0 + tx*4);
        stf4(out + row*Dn + c0 + tx*4,
             make_float4(acc[i][0] + xv.x, acc[i][1] + xv.y,
                         acc[i][2] + xv.z, acc[i][3] + xv.w));
    }
}

// ---------------- launcher ----------------
extern "C" void kernel_launch(void* const* d_in, const int* in_sizes, int n_in,
                              void* d_out, int out_size)
{
    const float* x       = (const float*)d_in[0];
    const float* W_write = (const float*)d_in[1];
    const float* W_gate  = (const float*)d_in[2];
    const float* W_out   = (const float*)d_in[3];
    const float* W_beta  = (const float*)d_in[4];
    const float* W_alpha = (const float*)d_in[5];
    const float* dt_bias = (const float*)d_in[6];
    const float* A_log   = (const float*)d_in[7];
    float* out = (float*)d_out;

    cudaFuncSetAttribute(k_chunk, cudaFuncAttributeMaxDynamicSharedMemorySize, (int)SMEM_CHUNK);
    cudaFuncSetAttribute(k_scan,  cudaFuncAttributeMaxDynamicSharedMemorySize, (int)SMEM_SCAN);

    k_proj_small<<<BT, 256>>>(x, W_gate, W_beta, W_alpha, dt_bias, A_log);
    k_rkwk<<<BT, 256>>>(x);
    k_cumsum<<<(BH*Nc + 255)/256, 256>>>();
    k_gemm_v<<<dim3(Dn/64, BT/64), 256>>>(x, W_write);
    k_chunk<<<BH*Nc, 256, SMEM_CHUNK>>>();
    k_scan<<<BH*ESPLIT, 256, SMEM_SCAN>>>();
    k_gemm_out<<<dim3(Dn/64, BT/64), 256>>>(W_out, x, out);
}

// round 3
// speedup vs baseline: 1.0008x; 1.0008x over previous
#include <cuda_runtime.h>
#include <math.h>

#define Bn 4
#define Tn 8192
#define Dn 1024
#define Hn 8
#define HDm 128
#define Cc 64
#define Nc 128
#define BT (Bn*Tn)
#define BH (Bn*Hn)
#define PAD 132
#define ESPLIT 4

// ---------------- scratch (device globals; no runtime allocation) ----------------
__device__ float g_rk  [(size_t)BH*Tn*HDm];   // normalized read keys   (B,H,T,d)
__device__ float g_wk  [(size_t)BH*Tn*HDm];   // shifted write keys     (B,H,T,d)
__device__ float g_v   [(size_t)BH*Tn*HDm];   // v (beta-scaled, then UT-transformed in place)
__device__ float g_wkcd[(size_t)BH*Tn*HDm];   // A @ (wk*beta*exp(dec))
__device__ float g_o   [(size_t)BT*Dn];       // gated output, (B,T,D)
__device__ float g_attn[(size_t)BH*Nc*Cc*Cc]; // intra-chunk attention (precomputed, S-independent)
__device__ float g_dec   [(size_t)BH*Tn];     // cumulative log-decay per chunk, (B,H,N,C)
__device__ float g_decraw[(size_t)BH*Tn];
__device__ float g_beta  [(size_t)BH*Tn];     // (B,H,T)
__device__ float g_gate  [(size_t)BT*Hn];     // (B,T,H)

static __device__ __forceinline__ float4 ldf4(const float* p) { return *(const float4*)p; }
static __device__ __forceinline__ void stf4(float* p, float4 v) { *(float4*)p = v; }

// ---------------- K1: gate/beta/decay projections ----------------
__global__ __launch_bounds__(256) void k_proj_small(
    const float* __restrict__ x, const float* __restrict__ Wg,
    const float* __restrict__ Wb, const float* __restrict__ Wa,
    const float* __restrict__ dtb, const float* __restrict__ Alog)
{
    int row = blockIdx.x;             // b*T + t
    int tid = threadIdx.x;
    __shared__ float sx[Dn];
    ((float4*)sx)[tid] = ((const float4*)(x + (size_t)row*Dn))[tid];
    __syncthreads();
    int w = tid >> 5, lane = tid & 31;   // warp w -> head w
    const float* wg = Wg + (size_t)w*Dn;
    const float* wb = Wb + (size_t)w*Dn;
    const float* wa = Wa + (size_t)w*Dn;
    float dg = 0.f, db = 0.f, da = 0.f;
    for (int k = lane*4; k < Dn; k += 128) {
        float4 xv = ldf4(sx + k);
        float4 g4 = ldf4(wg + k);
        float4 b4 = ldf4(wb + k);
        float4 a4 = ldf4(wa + k);
        dg += xv.x*g4.x + xv.y*g4.y + xv.z*g4.z + xv.w*g4.w;
        db += xv.x*b4.x + xv.y*b4.y + xv.z*b4.z + xv.w*b4.w;
        da += xv.x*a4.x + xv.y*a4.y + xv.z*a4.z + xv.w*a4.w;
    }
    #pragma unroll
    for (int o = 16; o; o >>= 1) {
        dg += __shfl_down_sync(0xffffffffu, dg, o);
        db += __shfl_down_sync(0xffffffffu, db, o);
        da += __shfl_down_sync(0xffffffffu, da, o);
    }
    if (lane == 0) {
        int b = row / Tn, t = row % Tn;
        g_gate[(size_t)row*Hn + w] = 1.f / (1.f + expf(-dg));
        size_t idx = (size_t)(b*Hn + w)*Tn + t;
        g_beta[idx] = 1.f / (1.f + expf(-db));
        float z = da + dtb[w];
        float sp = (z > 20.f) ? z : log1pf(expf(z));
        g_decraw[idx] = -expf(Alog[w]) * sp;
    }
}

// ---------------- K2: normalized read keys + token-shifted write keys ----------------
__global__ __launch_bounds__(256) void k_rkwk(const float* __restrict__ x)
{
    int row = blockIdx.x;             // b*T + t
    int b = row / Tn, t = row % Tn;
    int tid = threadIdx.x, w = tid >> 5, lane = tid & 31;
    const float* xr = x + (size_t)row*Dn + w*HDm;
    float4 v = ((const float4*)xr)[lane];
    float ss = v.x*v.x + v.y*v.y + v.z*v.z + v.w*v.w;
    #pragma unroll
    for (int o = 16; o; o >>= 1) ss += __shfl_xor_sync(0xffffffffu, ss, o);
    float inv = 1.f / fmaxf(sqrtf(ss), 1e-12f);
    float4 r = make_float4(v.x*inv, v.y*inv, v.z*inv, v.w*inv);
    size_t base = (size_t)(b*Hn + w)*Tn;
    ((float4*)(g_rk + (base + t)*HDm))[lane] = r;
    if (t + 1 < Tn) ((float4*)(g_wk + (base + t + 1)*HDm))[lane] = r;
    if (t == 0) {
        float4 z = make_float4(0.f, 0.f, 0.f, 0.f);
        ((float4*)(g_wk + base*HDm))[lane] = z;
    }
}

// ---------------- K3: per-chunk cumulative decay ----------------
__global__ void k_cumsum()
{
    int idx = blockIdx.x*blockDim.x + threadIdx.x;   // (b*H+h)*N + n
    if (idx >= BH*Nc) return;
    const float* src = g_decraw + (size_t)idx*Cc;
    float* dst = g_dec + (size_t)idx*Cc;
    float s = 0.f;
    for (int c = 0; c < Cc; c++) { s += src[c]; dst[c] = s; }
}

// ---------------- K4: v = (x @ W_write^T) * beta, scattered to (B,H,T,d) ----------------
__global__ __launch_bounds__(256) void k_gemm_v(const float* __restrict__ A,
                                                const float* __restrict__ W)
{
    __shared__ float As[16][68];
    __shared__ float Bs[16][68];
    int tid = threadIdx.x;
    int r0 = blockIdx.y*64, c0 = blockIdx.x*64;
    int tx = tid & 15, ty = tid >> 4;
    int lr = tid >> 2, kq = tid & 3;
    float acc[4][4] = {};
    const float* Ap = A + (size_t)(r0 + lr)*Dn + kq*4;
    const float* Wp = W + (size_t)(c0 + lr)*Dn + kq*4;
    for (int k0 = 0; k0 < Dn; k0 += 16) {
        float4 av = ldf4(Ap + k0);
        float4 bv = ldf4(Wp + k0);
        As[kq*4+0][lr]=av.x; As[kq*4+1][lr]=av.y; As[kq*4+2][lr]=av.z; As[kq*4+3][lr]=av.w;
        Bs[kq*4+0][lr]=bv.x; Bs[kq*4+1][lr]=bv.y; Bs[kq*4+2][lr]=bv.z; Bs[kq*4+3][lr]=bv.w;
        __syncthreads();
        #pragma unroll
        for (int k = 0; k < 16; k++) {
            float4 ra = ldf4(&As[k][ty*4]);
            float4 rb = ldf4(&Bs[k][tx*4]);
            float a_[4] = {ra.x, ra.y, ra.z, ra.w};
            float b_[4] = {rb.x, rb.y, rb.z, rb.w};
            #pragma unroll
            for (int i = 0; i < 4; i++)
                #pragma unroll
                for (int j = 0; j < 4; j++)
                    acc[i][j] += a_[i]*b_[j];
        }
        __syncthreads();
    }
    int b = r0 / Tn;
    int h = c0 / HDm;
    int kk0 = (c0 % HDm) + tx*4;
    #pragma unroll
    for (int i = 0; i < 4; i++) {
        int t = (r0 % Tn) + ty*4 + i;
        size_t bht = (size_t)(b*Hn + h)*Tn + t;
        float bb = g_beta[bht];
        stf4(g_v + bht*HDm + kk0,
             make_float4(acc[i][0]*bb, acc[i][1]*bb, acc[i][2]*bb, acc[i][3]*bb));
    }
}

// ---------------- K5: per-chunk UT transform + attn precompute ----------------
// smem floats: 3*64*PAD + 128*64 + 64*68 + 192 = 38080  (152320 B)
#define SMEM_CHUNK (size_t)((3*64*PAD + 128*64 + 64*68 + 192)*4)
__global__ __launch_bounds__(256) void k_chunk()
{
    extern __shared__ float sm[];
    float* s_wk   = sm;                 // 64*PAD
    float* s_rk   = s_wk  + 64*PAD;
    float* s_v    = s_rk  + 64*PAD;
    float* s_wkT  = s_v   + 64*PAD;     // 128*64 (k-major wk for conflict-free B operand)
    float* s_M    = s_wkT + 128*64;     // 64*68  (M -> A in place, strict lower)
    float* s_dec  = s_M   + 64*68;      // 64
    float* s_beta = s_dec + 64;
    float* s_edec = s_beta + 64;

    int chunk = blockIdx.x;             // (b*H+h)*N + n
    size_t base = (size_t)chunk*(Cc*HDm);
    int tid = threadIdx.x;

    for (int i4 = tid; i4 < 64*32; i4 += 256) {
        int r = i4 >> 5, c4 = (i4 & 31)*4;
        float4 wv = ldf4(g_wk + base + (size_t)r*HDm + c4);
        stf4(s_wk + r*PAD + c4, wv);
        s_wkT[(c4+0)*64 + r] = wv.x;
        s_wkT[(c4+1)*64 + r] = wv.y;
        s_wkT[(c4+2)*64 + r] = wv.z;
        s_wkT[(c4+3)*64 + r] = wv.w;
        stf4(s_rk + r*PAD + c4, ldf4(g_rk + base + (size_t)r*HDm + c4));
        stf4(s_v  + r*PAD + c4, ldf4(g_v  + base + (size_t)r*HDm + c4));
    }
    if (tid < 64) {
        s_dec[tid]  = g_dec [(size_t)chunk*Cc + tid];
        s_beta[tid] = g_beta[(size_t)chunk*Cc + tid];
    }
    __syncthreads();
    if (tid < 64) s_edec[tid] = expf(s_dec[tid]);

    // ---- M (strict lower, beta*exp masked) and attn (incl. diag), both 64x64 ----
    int j0 = (tid & 15)*4;
    int ibase = tid >> 4;
    #pragma unroll
    for (int ib = 0; ib < 4; ib++) {
        int i = ibase + 16*ib;
        float mA[4] = {0,0,0,0};
        float aA[4] = {0,0,0,0};
        const float* wkr = s_wk + i*PAD;
        const float* rkr = s_rk + i*PAD;
        for (int k = 0; k < HDm; k++) {
            float wik = wkr[k], rik = rkr[k];
            float4 wj = ldf4(s_wkT + k*64 + j0);
            mA[0] += wik*wj.x; mA[1] += wik*wj.y; mA[2] += wik*wj.z; mA[3] += wik*wj.w;
            aA[0] += rik*wj.x; aA[1] += rik*wj.y; aA[2] += rik*wj.z; aA[3] += rik*wj.w;
        }
        float di = s_dec[i], bi = s_beta[i];
        float av[4], mv[4];
        #pragma unroll
        for (int q = 0; q < 4; q++) {
            int j = j0 + q;
            float e = expf(di - s_dec[j]);
            av[q] = (j <= i) ? aA[q]*e : 0.f;
            mv[q] = (j <  i) ? mA[q]*bi*e : 0.f;
        }
        stf4(g_attn + (size_t)chunk*(Cc*Cc) + (size_t)i*Cc + j0,
             make_float4(av[0], av[1], av[2], av[3]));
        stf4(s_M + i*68 + j0, make_float4(mv[0], mv[1], mv[2], mv[3]));
    }
    __syncthreads();

    // ---- forward substitution: A = (I+M)^-1, strict lower in place ----
    for (int i = 1; i < Cc; i++) {
        float a = 0.f;
        if (tid < i) {
            a = s_M[i*68 + tid];
            for (int k = tid + 1; k < i; k++)
                a += s_M[i*68 + k] * s_M[k*68 + tid];
            a = -a;
        }
        __syncthreads();
        if (tid < i) s_M[i*68 + tid] = a;
        __syncthreads();
    }

    // ---- v_new = A @ v ; wkcd = A @ (wk*beta*exp(dec)) ----
    int k0 = (tid & 31)*4;
    int cbase = tid >> 5;
    #pragma unroll
    for (int cb = 0; cb < 8; cb++) {
        int c = cbase + 8*cb;
        float4 vac = ldf4(s_v + c*PAD + k0);
        float cw = s_beta[c]*s_edec[c];
        float4 wc = ldf4(s_wk + c*PAD + k0);
        float4 wac = make_float4(wc.x*cw, wc.y*cw, wc.z*cw, wc.w*cw);
        for (int j = 0; j < c; j++) {
            float aa = s_M[c*68 + j];
            float4 vj = ldf4(s_v + j*PAD + k0);
            float4 wj = ldf4(s_wk + j*PAD + k0);
            float cj = aa * s_beta[j] * s_edec[j];
            vac.x += aa*vj.x; vac.y += aa*vj.y; vac.z += aa*vj.z; vac.w += aa*vj.w;
            wac.x += cj*wj.x; wac.y += cj*wj.y; wac.z += cj*wj.z; wac.w += cj*wj.w;
        }
        stf4(g_v    + base + (size_t)c*HDm + k0, vac);
        stf4(g_wkcd + base + (size_t)c*HDm + k0, wac);
    }
}

// ---------------- K6: sequential inter-chunk scan (state S), e-split x4 ----------------
// smem floats: 128*32 + 3*64*PAD + 64*68 + 64*32 + 208 = 36096  (144384 B)
#define SMEM_SCAN (size_t)((128*32 + 3*64*PAD + 64*68 + 64*32 + 208)*4)
__global__ __launch_bounds__(256) void k_scan()
{
    extern __shared__ float sm[];
    float* s_S    = sm;                    // 128*32
    float* s_rk   = s_S    + 128*32;       // 64*PAD
    float* s_wk   = s_rk   + 64*PAD;
    float* s_wkcd = s_wk   + 64*PAD;
    float* s_attn = s_wkcd + 64*PAD;       // 64*68
    float* s_vnew = s_attn + 64*68;        // 64*32
    float* s_dec  = s_vnew + 64*32;        // 64
    float* s_edec = s_dec  + 64;
    float* s_coef = s_edec + 64;
    float* s_edl  = s_coef + 64;           // 16 slack

    int bh = blockIdx.x >> 2;
    int es = blockIdx.x & 3;
    int b = bh / Hn, h = bh % Hn;
    int tid = threadIdx.x;
    for (int i = tid; i < 128*32; i += 256) s_S[i] = 0.f;

    int e4 = tid & 7;
    int eoff = e4*4;
    int cA = tid >> 3;                     // 0..31
    int ecol = es*32 + eoff;
    size_t bhbase = (size_t)bh*Tn*HDm;

    for (int n = 0; n < Nc; n++) {
        size_t cb = bhbase + (size_t)n*Cc*HDm;
        for (int i4 = tid; i4 < 64*32; i4 += 256) {
            int r = i4 >> 5, c4 = (i4 & 31)*4;
            stf4(s_rk   + r*PAD + c4, ldf4(g_rk   + cb + (size_t)r*HDm + c4));
            stf4(s_wk   + r*PAD + c4, ldf4(g_wk   + cb + (size_t)r*HDm + c4));
            stf4(s_wkcd + r*PAD + c4, ldf4(g_wkcd + cb + (size_t)r*HDm + c4));
        }
        size_t ab = ((size_t)bh*Nc + n)*(Cc*Cc);
        for (int i4 = tid; i4 < 64*16; i4 += 256) {
            int r = i4 >> 4, c4 = (i4 & 15)*4;
            stf4(s_attn + r*68 + c4, ldf4(g_attn + ab + (size_t)r*Cc + c4));
        }
        if (tid < 64) s_dec[tid] = g_dec[((size_t)bh*Nc + n)*Cc + tid];
        __syncthreads();
        if (tid < 64) {
            float dl = s_dec[63];
            s_edec[tid] = expf(s_dec[tid]);
            s_coef[tid] = expf(dl - s_dec[tid]);
            if (tid == 0) s_edl[0] = expf(dl);
        }
        // ---- Phase A: v_new = v - wkcd @ S ----
        float4 va0 = ldf4(g_v + cb + (size_t)cA*HDm + ecol);
        float4 va1 = ldf4(g_v + cb + (size_t)(cA+32)*HDm + ecol);
        for (int k = 0; k < HDm; k++) {
            float4 S4 = ldf4(s_S + k*32 + eoff);
            float w0 = s_wkcd[cA*PAD + k];
            float w1 = s_wkcd[(cA+32)*PAD + k];
            va0.x -= w0*S4.x; va0.y -= w0*S4.y; va0.z -= w0*S4.z; va0.w -= w0*S4.w;
            va1.x -= w1*S4.x; va1.y -= w1*S4.y; va1.z -= w1*S4.z; va1.w -= w1*S4.w;
        }
        stf4(s_vnew + cA*32 + eoff, va0);
        stf4(s_vnew + (cA+32)*32 + eoff, va1);
        __syncthreads();
        // ---- Phase B: o = (rk*exp(dec)) @ S + attn @ v_new, gated ----
        float4 p0 = make_float4(0,0,0,0), p1 = make_float4(0,0,0,0);
        for (int k = 0; k < HDm; k++) {
            float4 S4 = ldf4(s_S + k*32 + eoff);
            float r0v = s_rk[cA*PAD + k];
            float r1v = s_rk[(cA+32)*PAD + k];
            p0.x += r0v*S4.x; p0.y += r0v*S4.y; p0.z += r0v*S4.z; p0.w += r0v*S4.w;
            p1.x += r1v*S4.x; p1.y += r1v*S4.y; p1.z += r1v*S4.z; p1.w += r1v*S4.w;
        }
        float ed0 = s_edec[cA], ed1 = s_edec[cA+32];
        float4 o0 = make_float4(p0.x*ed0, p0.y*ed0, p0.z*ed0, p0.w*ed0);
        float4 o1 = make_float4(p1.x*ed1, p1.y*ed1, p1.z*ed1, p1.w*ed1);
        for (int j = 0; j < Cc; j++) {                 // attn upper triangle is 0
            float4 vn = ldf4(s_vnew + j*32 + eoff);
            float a0 = s_attn[cA*68 + j];
            float a1 = s_attn[(cA+32)*68 + j];
            o0.x += a0*vn.x; o0.y += a0*vn.y; o0.z += a0*vn.z; o0.w += a0*vn.w;
            o1.x += a1*vn.x; o1.y += a1*vn.y; o1.z += a1*vn.z; o1.w += a1*vn.w;
        }
        {
            int t0 = n*Cc + cA, t1 = t0 + 32;
            float gg0 = g_gate[((size_t)b*Tn + t0)*Hn + h];
            float gg1 = g_gate[((size_t)b*Tn + t1)*Hn + h];
            o0.x *= gg0; o0.y *= gg0; o0.z *= gg0; o0.w *= gg0;
            o1.x *= gg1; o1.y *= gg1; o1.z *= gg1; o1.w *= gg1;
            stf4(g_o + ((size_t)b*Tn + t0)*Dn + h*HDm + ecol, o0);
            stf4(g_o + ((size_t)b*Tn + t1)*Dn + h*HDm + ecol, o1);
        }
        __syncthreads();
        // ---- Phase C: S = S*exp(dec_last) + (wk*exp(dec_last-dec))^T @ v_new ----
        float edl = s_edl[0];
        #pragma unroll
        for (int q = 0; q < 4; q++) {
            int k = cA + 32*q;
            float4 s4 = ldf4(s_S + k*32 + eoff);
            s4.x *= edl; s4.y *= edl; s4.z *= edl; s4.w *= edl;
            for (int c = 0; c < Cc; c++) {
                float wc = s_wk[c*PAD + k] * s_coef[c];
                float4 vn = ldf4(s_vnew + c*32 + eoff);
                s4.x += wc*vn.x; s4.y += wc*vn.y; s4.z += wc*vn.z; s4.w += wc*vn.w;
            }
            stf4(s_S + k*32 + eoff, s4);
        }
        __syncthreads();
    }
}

// ---------------- K7: out = x + o @ W_out^T ----------------
__global__ __launch_bounds__(256) void k_gemm_out(const float* __restrict__ W,
                                                  const float* __restrict__ x,
                                                  float* __restrict__ out)
{
    __shared__ float As[16][68];
    __shared__ float Bs[16][68];
    int tid = threadIdx.x;
    int r0 = blockIdx.y*64, c0 = blockIdx.x*64;
    int tx = tid & 15, ty = tid >> 4;
    int lr = tid >> 2, kq = tid & 3;
    float acc[4][4] = {};
    const float* Ap = g_o + (size_t)(r0 + lr)*Dn + kq*4;
    const float* Wp = W + (size_t)(c0 + lr)*Dn + kq*4;
    for (int k0 = 0; k0 < Dn; k0 += 16) {
        float4 av = ldf4(Ap + k0);
        float4 bv = ldf4(Wp + k0);
        As[kq*4+0][lr]=av.x; As[kq*4+1][lr]=av.y; As[kq*4+2][lr]=av.z; As[kq*4+3][lr]=av.w;
        Bs[kq*4+0][lr]=bv.x; Bs[kq*4+1][lr]=bv.y; Bs[kq*4+2][lr]=bv.z; Bs[kq*4+3][lr]=bv.w;
        __syncthreads();
        #pragma unroll
        for (int k = 0; k < 16; k++) {
            float4 ra = ldf4(&As[k][ty*4]);
            float4 rb = ldf4(&Bs[k][tx*4]);
            float a_[4] = {ra.x, ra.y, ra.z, ra.w};
            float b_[4] = {rb.x, rb.y, rb.z, rb.w};
            #pragma unroll
            for (int i = 0; i < 4; i++)
                #pragma unroll
                for (int j = 0; j < 4; j++)
                    acc[i][j] += a_[i]*b_[j];
        }
        __syncthreads();
    }
    #pragma unroll
    for (int i = 0; i < 4; i++) {
        size_t row = (size_t)r0 + ty*4 + i;
        float4 xv = ldf4(x + row*Dn + c0 + tx*4);
        stf4(out + row*Dn + c0 + tx*4,
             make_float4(acc[i][0] + xv.x, acc[i][1] + xv.y,
                         acc[i][2] + xv.z, acc[i][3] + xv.w));
    }
}

// ---------------- launcher ----------------
extern "C" void kernel_launch(void* const* d_in, const int* in_sizes, int n_in,
                              void* d_out, int out_size)
{
    const float* x       = (const float*)d_in[0];
    const float* W_write = (const float*)d_in[1];
    const float* W_gate  = (const float*)d_in[2];
    const float* W_out   = (const float*)d_in[3];
    const float* W_beta  = (const float*)d_in[4];
    const float* W_alpha = (const float*)d_in[5];
    const float* dt_bias = (const float*)d_in[6];
    const float* A_log   = (const float*)d_in[7];
    float* out = (float*)d_out;

    cudaFuncSetAttribute(k_chunk, cudaFuncAttributeMaxDynamicSharedMemorySize, (int)SMEM_CHUNK);
    cudaFuncSetAttribute(k_scan,  cudaFuncAttributeMaxDynamicSharedMemorySize, (int)SMEM_SCAN);

    k_proj_small<<<BT, 256>>>(x, W_gate, W_beta, W_alpha, dt_bias, A_log);
    k_rkwk<<<BT, 256>>>(x);
    k_cumsum<<<(BH*Nc + 255)/256, 256>>>();
    k_gemm_v<<<dim3(Dn/64, BT/64), 256>>>(x, W_write);
    k_chunk<<<BH*Nc, 256, SMEM_CHUNK>>>();
    k_scan<<<BH*ESPLIT, 256, SMEM_SCAN>>>();
    k_gemm_out<<<dim3(Dn/64, BT/64), 256>>>(W_out, x, out);
}

// round 5
// speedup vs baseline: 1.0011x; 1.0003x over previous
#include <cuda_runtime.h>
#include <math.h>

#define Bn 4
#define Tn 8192
#define Dn 1024
#define Hn 8
#define HDm 128
#define Cc 64
#define Nc 128
#define BT (Bn*Tn)
#define BH (Bn*Hn)
#define PAD 132
#define ESPLIT 4

// ---------------- scratch (device globals; no runtime allocation) ----------------
__device__ float g_rk  [(size_t)BH*Tn*HDm];   // normalized read keys   (B,H,T,d)
__device__ float g_wk  [(size_t)BH*Tn*HDm];   // shifted write keys     (B,H,T,d)
__device__ float g_v   [(size_t)BH*Tn*HDm];   // v (beta-scaled, then UT-transformed in place)
__device__ float g_wkcd[(size_t)BH*Tn*HDm];   // A @ (wk*beta*exp(dec))
__device__ float g_o   [(size_t)BT*Dn];       // gated output, (B,T,D)
__device__ float g_attn[(size_t)BH*Nc*Cc*Cc]; // intra-chunk attention (precomputed, S-independent)
__device__ float g_dec   [(size_t)BH*Tn];     // cumulative log-decay per chunk, (B,H,N,C)
__device__ float g_decraw[(size_t)BH*Tn];
__device__ float g_beta  [(size_t)BH*Tn];     // (B,H,T)
__device__ float g_gate  [(size_t)BT*Hn];     // (B,T,H)

static __device__ __forceinline__ float4 ldf4(const float* p) { return *(const float4*)p; }
static __device__ __forceinline__ void stf4(float* p, float4 v) { *(float4*)p = v; }

// ---------------- K1: gate/beta/decay projections ----------------
__global__ __launch_bounds__(256) void k_proj_small(
    const float* __restrict__ x, const float* __restrict__ Wg,
    const float* __restrict__ Wb, const float* __restrict__ Wa,
    const float* __restrict__ dtb, const float* __restrict__ Alog)
{
    int row = blockIdx.x;             // b*T + t
    int tid = threadIdx.x;
    __shared__ float sx[Dn];
    ((float4*)sx)[tid] = ((const float4*)(x + (size_t)row*Dn))[tid];
    __syncthreads();
    int w = tid >> 5, lane = tid & 31;   // warp w -> head w
    const float* wg = Wg + (size_t)w*Dn;
    const float* wb = Wb + (size_t)w*Dn;
    const float* wa = Wa + (size_t)w*Dn;
    float dg = 0.f, db = 0.f, da = 0.f;
    for (int k = lane*4; k < Dn; k += 128) {
        float4 xv = ldf4(sx + k);
        float4 g4 = ldf4(wg + k);
        float4 b4 = ldf4(wb + k);
        float4 a4 = ldf4(wa + k);
        dg += xv.x*g4.x + xv.y*g4.y + xv.z*g4.z + xv.w*g4.w;
        db += xv.x*b4.x + xv.y*b4.y + xv.z*b4.z + xv.w*b4.w;
        da += xv.x*a4.x + xv.y*a4.y + xv.z*a4.z + xv.w*a4.w;
    }
    #pragma unroll
    for (int o = 16; o; o >>= 1) {
        dg += __shfl_down_sync(0xffffffffu, dg, o);
        db += __shfl_down_sync(0xffffffffu, db, o);
        da += __shfl_down_sync(0xffffffffu, da, o);
    }
    if (lane == 0) {
        int b = row / Tn, t = row % Tn;
        g_gate[(size_t)row*Hn + w] = 1.f / (1.f + expf(-dg));
        size_t idx = (size_t)(b*Hn + w)*Tn + t;
        g_beta[idx] = 1.f / (1.f + expf(-db));
        float z = da + dtb[w];
        float sp = (z > 20.f) ? z : log1pf(expf(z));
        g_decraw[idx] = -expf(Alog[w]) * sp;
    }
}

// ---------------- K2: normalized read keys + token-shifted write keys ----------------
__global__ __launch_bounds__(256) void k_rkwk(const float* __restrict__ x)
{
    int row = blockIdx.x;             // b*T + t
    int b = row / Tn, t = row % Tn;
    int tid = threadIdx.x, w = tid >> 5, lane = tid & 31;
    const float* xr = x + (size_t)row*Dn + w*HDm;
    float4 v = ((const float4*)xr)[lane];
    float ss = v.x*v.x + v.y*v.y + v.z*v.z + v.w*v.w;
    #pragma unroll
    for (int o = 16; o; o >>= 1) ss += __shfl_xor_sync(0xffffffffu, ss, o);
    float inv = 1.f / fmaxf(sqrtf(ss), 1e-12f);
    float4 r = make_float4(v.x*inv, v.y*inv, v.z*inv, v.w*inv);
    size_t base = (size_t)(b*Hn + w)*Tn;
    ((float4*)(g_rk + (base + t)*HDm))[lane] = r;
    if (t + 1 < Tn) ((float4*)(g_wk + (base + t + 1)*HDm))[lane] = r;
    if (t == 0) {
        float4 z = make_float4(0.f, 0.f, 0.f, 0.f);
        ((float4*)(g_wk + base*HDm))[lane] = z;
    }
}

// ---------------- K3: per-chunk cumulative decay ----------------
__global__ void k_cumsum()
{
    int idx = blockIdx.x*blockDim.x + threadIdx.x;   // (b*H+h)*N + n
    if (idx >= BH*Nc) return;
    const float* src = g_decraw + (size_t)idx*Cc;
    float* dst = g_dec + (size_t)idx*Cc;
    float s = 0.f;
    for (int c = 0; c < Cc; c++) { s += src[c]; dst[c] = s; }
}

// ---------------- K4: v = (x @ W_write^T) * beta, scattered to (B,H,T,d) ----------------
__global__ __launch_bounds__(256) void k_gemm_v(const float* __restrict__ A,
                                                const float* __restrict__ W)
{
    __shared__ float As[16][68];
    __shared__ float Bs[16][68];
    int tid = threadIdx.x;
    int r0 = blockIdx.y*64, c0 = blockIdx.x*64;
    int tx = tid & 15, ty = tid >> 4;
    int lr = tid >> 2, kq = tid & 3;
    float acc[4][4] = {};
    const float* Ap = A + (size_t)(r0 + lr)*Dn + kq*4;
    const float* Wp = W + (size_t)(c0 + lr)*Dn + kq*4;
    for (int k0 = 0; k0 < Dn; k0 += 16) {
        float4 av = ldf4(Ap + k0);
        float4 bv = ldf4(Wp + k0);
        As[kq*4+0][lr]=av.x; As[kq*4+1][lr]=av.y; As[kq*4+2][lr]=av.z; As[kq*4+3][lr]=av.w;
        Bs[kq*4+0][lr]=bv.x; Bs[kq*4+1][lr]=bv.y; Bs[kq*4+2][lr]=bv.z; Bs[kq*4+3][lr]=bv.w;
        __syncthreads();
        #pragma unroll
        for (int k = 0; k < 16; k++) {
            float4 ra = ldf4(&As[k][ty*4]);
            float4 rb = ldf4(&Bs[k][tx*4]);
            float a_[4] = {ra.x, ra.y, ra.z, ra.w};
            float b_[4] = {rb.x, rb.y, rb.z, rb.w};
            #pragma unroll
            for (int i = 0; i < 4; i++)
                #pragma unroll
                for (int j = 0; j < 4; j++)
                    acc[i][j] += a_[i]*b_[j];
        }
        __syncthreads();
    }
    int b = r0 / Tn;
    int h = c0 / HDm;
    int kk0 = (c0 % HDm) + tx*4;
    #pragma unroll
    for (int i = 0; i < 4; i++) {
        int t = (r0 % Tn) + ty*4 + i;
        size_t bht = (size_t)(b*Hn + h)*Tn + t;
        float bb = g_beta[bht];
        stf4(g_v + bht*HDm + kk0,
             make_float4(acc[i][0]*bb, acc[i][1]*bb, acc[i][2]*bb, acc[i][3]*bb));
    }
}

// ---------------- K5: per-chunk UT transform + attn precompute ----------------
// smem floats: 3*64*PAD + 128*64 + 64*68 + 192 = 38080  (152320 B)
#define SMEM_CHUNK (size_t)((3*64*PAD + 128*64 + 64*68 + 192)*4)
__global__ __launch_bounds__(256) void k_chunk()
{
    extern __shared__ float sm[];
    float* s_wk   = sm;                 // 64*PAD
    float* s_rk   = s_wk  + 64*PAD;
    float* s_v    = s_rk  + 64*PAD;
    float* s_wkT  = s_v   + 64*PAD;     // 128*64 (k-major wk for conflict-free B operand)
    float* s_M    = s_wkT + 128*64;     // 64*68  (M -> A in place, strict lower)
    float* s_dec  = s_M   + 64*68;      // 64
    float* s_beta = s_dec + 64;
    float* s_edec = s_beta + 64;

    int chunk = blockIdx.x;             // (b*H+h)*N + n
    size_t base = (size_t)chunk*(Cc*HDm);
    int tid = threadIdx.x;

    for (int i4 = tid; i4 < 64*32; i4 += 256) {
        int r = i4 >> 5, c4 = (i4 & 31)*4;
        float4 wv = ldf4(g_wk + base + (size_t)r*HDm + c4);
        stf4(s_wk + r*PAD + c4, wv);
        s_wkT[(c4+0)*64 + r] = wv.x;
        s_wkT[(c4+1)*64 + r] = wv.y;
        s_wkT[(c4+2)*64 + r] = wv.z;
        s_wkT[(c4+3)*64 + r] = wv.w;
        stf4(s_rk + r*PAD + c4, ldf4(g_rk + base + (size_t)r*HDm + c4));
        stf4(s_v  + r*PAD + c4, ldf4(g_v  + base + (size_t)r*HDm + c4));
    }
    if (tid < 64) {
        s_dec[tid]  = g_dec [(size_t)chunk*Cc + tid];
        s_beta[tid] = g_beta[(size_t)chunk*Cc + tid];
    }
    __syncthreads();
    if (tid < 64) s_edec[tid] = expf(s_dec[tid]);

    // ---- M (strict lower, beta*exp masked) and attn (incl. diag), both 64x64 ----
    int j0 = (tid & 15)*4;
    int ibase = tid >> 4;
    #pragma unroll
    for (int ib = 0; ib < 4; ib++) {
        int i = ibase + 16*ib;
        float mA[4] = {0,0,0,0};
        float aA[4] = {0,0,0,0};
        const float* wkr = s_wk + i*PAD;
        const float* rkr = s_rk + i*PAD;
        for (int k = 0; k < HDm; k++) {
            float wik = wkr[k], rik = rkr[k];
            float4 wj = ldf4(s_wkT + k*64 + j0);
            mA[0] += wik*wj.x; mA[1] += wik*wj.y; mA[2] += wik*wj.z; mA[3] += wik*wj.w;
            aA[0] += rik*wj.x; aA[1] += rik*wj.y; aA[2] += rik*wj.z; aA[3] += rik*wj.w;
        }
        float di = s_dec[i], bi = s_beta[i];
        float av[4], mv[4];
        #pragma unroll
        for (int q = 0; q < 4; q++) {
            int j = j0 + q;
            float e = expf(di - s_dec[j]);
            av[q] = (j <= i) ? aA[q]*e : 0.f;
            mv[q] = (j <  i) ? mA[q]*bi*e : 0.f;
        }
        stf4(g_attn + (size_t)chunk*(Cc*Cc) + (size_t)i*Cc + j0,
             make_float4(av[0], av[1], av[2], av[3]));
        stf4(s_M + i*68 + j0, make_float4(mv[0], mv[1], mv[2], mv[3]));
    }
    __syncthreads();

    // ---- forward substitution: A = (I+M)^-1, strict lower in place ----
    for (int i = 1; i < Cc; i++) {
        float a = 0.f;
        if (tid < i) {
            a = s_M[i*68 + tid];
            for (int k = tid + 1; k < i; k++)
                a += s_M[i*68 + k] * s_M[k*68 + tid];
            a = -a;
        }
        __syncthreads();
        if (tid < i) s_M[i*68 + tid] = a;
        __syncthreads();
    }

    // ---- v_new = A @ v ; wkcd = A @ (wk*beta*exp(dec)) ----
    int k0 = (tid & 31)*4;
    int cbase = tid >> 5;
    #pragma unroll
    for (int cb = 0; cb < 8; cb++) {
        int c = cbase + 8*cb;
        float4 vac = ldf4(s_v + c*PAD + k0);
        float cw = s_beta[c]*s_edec[c];
        float4 wc = ldf4(s_wk + c*PAD + k0);
        float4 wac = make_float4(wc.x*cw, wc.y*cw, wc.z*cw, wc.w*cw);
        for (int j = 0; j < c; j++) {
            float aa = s_M[c*68 + j];
            float4 vj = ldf4(s_v + j*PAD + k0);
            float4 wj = ldf4(s_wk + j*PAD + k0);
            float cj = aa * s_beta[j] * s_edec[j];
            vac.x += aa*vj.x; vac.y += aa*vj.y; vac.z += aa*vj.z; vac.w += aa*vj.w;
            wac.x += cj*wj.x; wac.y += cj*wj.y; wac.z += cj*wj.z; wac.w += cj*wj.w;
        }
        stf4(g_v    + base + (size_t)c*HDm + k0, vac);
        stf4(g_wkcd + base + (size_t)c*HDm + k0, wac);
    }
}

// ---------------- K6: sequential inter-chunk scan (state S), e-split x4 ----------------
// smem floats: 128*32 + 3*64*PAD + 64*68 + 64*32 + 208 = 36096  (144384 B)
#define SMEM_SCAN (size_t)((128*32 + 3*64*PAD + 64*68 + 64*32 + 208)*4)
__global__ __launch_bounds__(256) void k_scan()
{
    extern __shared__ float sm[];
    float* s_S    = sm;                    // 128*32
    float* s_rk   = s_S    + 128*32;       // 64*PAD
    float* s_wk   = s_rk   + 64*PAD;
    float* s_wkcd = s_wk   + 64*PAD;
    float* s_attn = s_wkcd + 64*PAD;       // 64*68
    float* s_vnew = s_attn + 64*68;        // 64*32
    float* s_dec  = s_vnew + 64*32;        // 64
    float* s_edec = s_dec  + 64;
    float* s_coef = s_edec + 64;
    float* s_edl  = s_coef + 64;           // 16 slack

    int bh = blockIdx.x >> 2;
    int es = blockIdx.x & 3;
    int b = bh / Hn, h = bh % Hn;
    int tid = threadIdx.x;
    for (int i = tid; i < 128*32; i += 256) s_S[i] = 0.f;

    int e4 = tid & 7;
    int eoff = e4*4;
    int cA = tid >> 3;                     // 0..31
    int ecol = es*32 + eoff;
    size_t bhbase = (size_t)bh*Tn*HDm;

    for (int n = 0; n < Nc; n++) {
        size_t cb = bhbase + (size_t)n*Cc*HDm;
        for (int i4 = tid; i4 < 64*32; i4 += 256) {
            int r = i4 >> 5, c4 = (i4 & 31)*4;
            stf4(s_rk   + r*PAD + c4, ldf4(g_rk   + cb + (size_t)r*HDm + c4));
            stf4(s_wk   + r*PAD + c4, ldf4(g_wk   + cb + (size_t)r*HDm + c4));
            stf4(s_wkcd + r*PAD + c4, ldf4(g_wkcd + cb + (size_t)r*HDm + c4));
        }
        size_t ab = ((size_t)bh*Nc + n)*(Cc*Cc);
        for (int i4 = tid; i4 < 64*16; i4 += 256) {
            int r = i4 >> 4, c4 = (i4 & 15)*4;
            stf4(s_attn + r*68 + c4, ldf4(g_attn + ab + (size_t)r*Cc + c4));
        }
        if (tid < 64) s_dec[tid] = g_dec[((size_t)bh*Nc + n)*Cc + tid];
        __syncthreads();
        if (tid < 64) {
            float dl = s_dec[63];
            s_edec[tid] = expf(s_dec[tid]);
            s_coef[tid] = expf(dl - s_dec[tid]);
            if (tid == 0) s_edl[0] = expf(dl);
        }
        // ---- Phase A: v_new = v - wkcd @ S ----
        float4 va0 = ldf4(g_v + cb + (size_t)cA*HDm + ecol);
        float4 va1 = ldf4(g_v + cb + (size_t)(cA+32)*HDm + ecol);
        for (int k = 0; k < HDm; k++) {
            float4 S4 = ldf4(s_S + k*32 + eoff);
            float w0 = s_wkcd[cA*PAD + k];
            float w1 = s_wkcd[(cA+32)*PAD + k];
            va0.x -= w0*S4.x; va0.y -= w0*S4.y; va0.z -= w0*S4.z; va0.w -= w0*S4.w;
            va1.x -= w1*S4.x; va1.y -= w1*S4.y; va1.z -= w1*S4.z; va1.w -= w1*S4.w;
        }
        stf4(s_vnew + cA*32 + eoff, va0);
        stf4(s_vnew + (cA+32)*32 + eoff, va1);
        __syncthreads();
        // ---- Phase B: o = (rk*exp(dec)) @ S + attn @ v_new, gated ----
        float4 p0 = make_float4(0,0,0,0), p1 = make_float4(0,0,0,0);
        for (int k = 0; k < HDm; k++) {
            float4 S4 = ldf4(s_S + k*32 + eoff);
            float r0v = s_rk[cA*PAD + k];
            float r1v = s_rk[(cA+32)*PAD + k];
            p0.x += r0v*S4.x; p0.y += r0v*S4.y; p0.z += r0v*S4.z; p0.w += r0v*S4.w;
            p1.x += r1v*S4.x; p1.y += r1v*S4.y; p1.z += r1v*S4.z; p1.w += r1v*S4.w;
        }
        float ed0 = s_edec[cA], ed1 = s_edec[cA+32];
        float4 o0 = make_float4(p0.x*ed0, p0.y*ed0, p0.z*ed0, p0.w*ed0);
        float4 o1 = make_float4(p1.x*ed1, p1.y*ed1, p1.z*ed1, p1.w*ed1);
        for (int j = 0; j < Cc; j++) {                 // attn upper triangle is 0
            float4 vn = ldf4(s_vnew + j*32 + eoff);
            float a0 = s_attn[cA*68 + j];
            float a1 = s_attn[(cA+32)*68 + j];
            o0.x += a0*vn.x; o0.y += a0*vn.y; o0.z += a0*vn.z; o0.w += a0*vn.w;
            o1.x += a1*vn.x; o1.y += a1*vn.y; o1.z += a1*vn.z; o1.w += a1*vn.w;
        }
        {
            int t0 = n*Cc + cA, t1 = t0 + 32;
            float gg0 = g_gate[((size_t)b*Tn + t0)*Hn + h];
            float gg1 = g_gate[((size_t)b*Tn + t1)*Hn + h];
            o0.x *= gg0; o0.y *= gg0; o0.z *= gg0; o0.w *= gg0;
            o1.x *= gg1; o1.y *= gg1; o1.z *= gg1; o1.w *= gg1;
            stf4(g_o + ((size_t)b*Tn + t0)*Dn + h*HDm + ecol, o0);
            stf4(g_o + ((size_t)b*Tn + t1)*Dn + h*HDm + ecol, o1);
        }
        __syncthreads();
        // ---- Phase C: S = S*exp(dec_last) + (wk*exp(dec_last-dec))^T @ v_new ----
        float edl = s_edl[0];
        #pragma unroll
        for (int q = 0; q < 4; q++) {
            int k = cA + 32*q;
            float4 s4 = ldf4(s_S + k*32 + eoff);
            s4.x *= edl; s4.y *= edl; s4.z *= edl; s4.w *= edl;
            for (int c = 0; c < Cc; c++) {
                float wc = s_wk[c*PAD + k] * s_coef[c];
                float4 vn = ldf4(s_vnew + c*32 + eoff);
                s4.x += wc*vn.x; s4.y += wc*vn.y; s4.z += wc*vn.z; s4.w += wc*vn.w;
            }
            stf4(s_S + k*32 + eoff, s4);
        }
        __syncthreads();
    }
}

// ---------------- K7: out = x + o @ W_out^T ----------------
__global__ __launch_bounds__(256) void k_gemm_out(const float* __restrict__ W,
                                                  const float* __restrict__ x,
                                                  float* __restrict__ out)
{
    __shared__ float As[16][68];
    __shared__ float Bs[16][68];
    int tid = threadIdx.x;
    int r0 = blockIdx.y*64, c0 = blockIdx.x*64;
    int tx = tid & 15, ty = tid >> 4;
    int lr = tid >> 2, kq = tid & 3;
    float acc[4][4] = {};
    const float* Ap = g_o + (size_t)(r0 + lr)*Dn + kq*4;
    const float* Wp = W + (size_t)(c0 + lr)*Dn + kq*4;
    for (int k0 = 0; k0 < Dn; k0 += 16) {
        float4 av = ldf4(Ap + k0);
        float4 bv = ldf4(Wp + k0);
        As[kq*4+0][lr]=av.x; As[kq*4+1][lr]=av.y; As[kq*4+2][lr]=av.z; As[kq*4+3][lr]=av.w;
        Bs[kq*4+0][lr]=bv.x; Bs[kq*4+1][lr]=bv.y; Bs[kq*4+2][lr]=bv.z; Bs[kq*4+3][lr]=bv.w;
        __syncthreads();
        #pragma unroll
        for (int k = 0; k < 16; k++) {
            float4 ra = ldf4(&As[k][ty*4]);
            float4 rb = ldf4(&Bs[k][tx*4]);
            float a_[4] = {ra.x, ra.y, ra.z, ra.w};
            float b_[4] = {rb.x, rb.y, rb.z, rb.w};
            #pragma unroll
            for (int i = 0; i < 4; i++)
                #pragma unroll
                for (int j = 0; j < 4; j++)
                    acc[i][j] += a_[i]*b_[j];
        }
        __syncthreads();
    }
    #pragma unroll
    for (int i = 0; i < 4; i++) {
        size_t row = (size_t)r0 + ty*4 + i;
        float4 xv = ldf4(x + row*Dn + c0 + tx*4);
        stf4(out + row*Dn + c0 + tx*4,
             make_float4(acc[i][0] + xv.x, acc[i][1] + xv.y,
                         acc[i][2] + xv.z, acc[i][3] + xv.w));
    }
}

// ---------------- launcher ----------------
extern "C" void kernel_launch(void* const* d_in, const int* in_sizes, int n_in,
                              void* d_out, int out_size)
{
    const float* x       = (const float*)d_in[0];
    const float* W_write = (const float*)d_in[1];
    const float* W_gate  = (const float*)d_in[2];
    const float* W_out   = (const float*)d_in[3];
    const float* W_beta  = (const float*)d_in[4];
    const float* W_alpha = (const float*)d_in[5];
    const float* dt_bias = (const float*)d_in[6];
    const float* A_log   = (const float*)d_in[7];
    float* out = (float*)d_out;

    cudaFuncSetAttribute(k_chunk, cudaFuncAttributeMaxDynamicSharedMemorySize, (int)SMEM_CHUNK);
    cudaFuncSetAttribute(k_scan,  cudaFuncAttributeMaxDynamicSharedMemorySize, (int)SMEM_SCAN);

    k_proj_small<<<BT, 256>>>(x, W_gate, W_beta, W_alpha, dt_bias, A_log);
    k_rkwk<<<BT, 256>>>(x);
    k_cumsum<<<(BH*Nc + 255)/256, 256>>>();
    k_gemm_v<<<dim3(Dn/64, BT/64), 256>>>(x, W_write);
    k_chunk<<<BH*Nc, 256, SMEM_CHUNK>>>();
    k_scan<<<BH*ESPLIT, 256, SMEM_SCAN>>>();
    k_gemm_out<<<dim3(Dn/64, BT/64), 256>>>(W_out, x, out);
}